// round 9
// baseline (speedup 1.0000x reference)
#include <cuda_runtime.h>
#include <math.h>

// Problem constants
#define NB 8
#define NK 1024
#define NL 1024
#define ND 1024
#define NO 6
#define NE 128

#define GRID 148
#define NTHR 1024
#define STRIDE (GRID * NTHR)

// Scratch (tiny): everything l-independent
__device__ __align__(16) float g_S [NB*NO*NE];   // raw vote sum  [b,o,e]
__device__ __align__(16) float g_Wv[NB*NO*ND];   // W @ v         [b,o,d]
__device__ __align__(16) float g_a [NB*NK*NO];   // logits        [b,k,o]
__device__ __align__(16) float g_p [NB*NK*NO];   // probs         [b,k,o]
__device__ __align__(16) float g_pu[NB*NO*ND];   // p^T @ u       [b,o,d]
__device__ int g_mask_is_u8;
__device__ volatile unsigned g_epoch;
__device__ unsigned g_arrive;

// smem layout offsets (floats); max use 6336 floats = 25.3 KB
#define SPU   4128          // S-phase pu stage   [8][32]
#define SV    4128          // Wv-phase v stage   [8][128]
#define SFAC  5152          // Wv-phase factors   [8]
#define SPART 5184          // Wv-phase partials  [4][8][32]
#define SP    6144          // apu probs stage    [32][6]
#define SF    6144          // out-phase factors  [48]

// ---------------------------------------------------------------------------
// Grid-wide barrier: epoch-counting, sense-free (monotonic across replays).
__device__ __forceinline__ void gsync() {
    __syncthreads();
    if (threadIdx.x == 0) {
        __threadfence();
        unsigned e = g_epoch;
        if (atomicAdd(&g_arrive, 1u) == GRID - 1) {
            g_arrive = 0;
            __threadfence();
            g_epoch = e + 1;
        } else {
            while (g_epoch == e) { __nanosleep(32); }
        }
        __threadfence();
    }
    __syncthreads();
}

__device__ __forceinline__ int mask_at(const unsigned char* mraw, size_t idx) {
    if (g_mask_is_u8) return mraw[idx] != 0;
    return ((const int*)mraw)[idx] != 0;
}

// ---------------------------------------------------------------------------
__global__ __launch_bounds__(NTHR, 1) void k_all(
    const float* __restrict__ u, const float* __restrict__ W,
    const unsigned char* __restrict__ mraw,
    float4* __restrict__ outv, float4* __restrict__ outp)
{
    __shared__ __align__(16) float sm[6400];
    const int tid = threadIdx.x;
    const int blk = blockIdx.x;

    // ===== Z: zero scratch, detect mask dtype =====
    for (int i = blk * NTHR + tid; i < NB*NO*ND; i += STRIDE) g_pu[i] = 0.f;
    for (int i = blk * NTHR + tid; i < NB*NO*NE; i += STRIDE) g_S[i]  = 0.f;
    if (blk == 0 && tid == 0) {
        int u8 = 0;
        for (int j = 0; j < 256; j++)
            if ((j & 3) != 0 && mraw[j] != 0) u8 = 1;
        g_mask_is_u8 = u8;
    }
    gsync();

    // ===== colsum: pu0 row (o=0) = sum_k u  (iter-0 uniform-softmax shortcut)
    for (int t = blk; t < 512; t += GRID) {
        int b  = t >> 6, r = t & 63;
        int d  = (r >> 4) * 256 + (tid & 255);
        int k0 = (r & 15) * 64 + (tid >> 8) * 16;
        const float* up = u + ((size_t)b * NK + k0) * ND + d;
        float acc = 0.f;
#pragma unroll
        for (int kk = 0; kk < 16; kk++) acc += up[(size_t)kk * ND];
        atomicAdd(&g_pu[(size_t)b * NO * ND + d], acc);
    }
    gsync();

    for (int it = 0; it < 3; it++) {
        // ===== S phase: S[b,o,e] += sum_d pu[b,o,d]*W[o,d,e]; tiles (o, 32d)
        for (int t = blk; t < 192; t += GRID) {
            int o = t / 32, dc = (t % 32) * 32;
            if (tid < 256) {
                int b = tid >> 5, dd = tid & 31;
                float v = (it == 0)
                    ? g_pu[(size_t)b * NO * ND + dc + dd] * (1.f / 6.f)
                    : g_pu[((size_t)b * NO + o) * ND + dc + dd];
                sm[SPU + tid] = v;
            }
            for (int i = tid; i < 32 * NE; i += NTHR) {
                int dd = i >> 7, e = i & 127;
                sm[dd * 129 + e] = W[((size_t)o * ND + dc + dd) * NE + e];
            }
            __syncthreads();
            int e = tid & 127, b = tid >> 7;
            float acc = 0.f;
#pragma unroll
            for (int dd = 0; dd < 32; dd++)
                acc += sm[SPU + b * 32 + dd] * sm[dd * 129 + e];
            atomicAdd(&g_S[((size_t)b * NO + o) * NE + e], acc);
            __syncthreads();
        }
        gsync();
        if (it == 2) break;

        // ===== WvSq phase: v=squash(S); Wv[b,o,d]=sum_e W[o,d,e]*v[b,o,e]
        // also zero g_pu for the coming apu accumulation
        for (int i = blk * NTHR + tid; i < NB*NO*ND; i += STRIDE) g_pu[i] = 0.f;
        for (int t = blk; t < 192; t += GRID) {
            int o = t / 32, dc = (t % 32) * 32;
            for (int i = tid; i < 32 * NE; i += NTHR) {
                int dd = i >> 7, e = i & 127;
                sm[dd * 129 + e] = W[((size_t)o * ND + dc + dd) * NE + e];
            }
            { int i = tid;  // 1024 entries, one each
              sm[SV + i] = g_S[((size_t)(i >> 7) * NO + o) * NE + (i & 127)]; }
            __syncthreads();
            int wid = tid >> 5, lane = tid & 31;
            if (wid < NB) {
                float sq = 0.f;
#pragma unroll
                for (int j = 0; j < 4; j++) {
                    float x = sm[SV + wid * NE + lane + 32 * j];
                    sq += x * x;
                }
#pragma unroll
                for (int off = 16; off; off >>= 1) sq += __shfl_xor_sync(0xffffffffu, sq, off);
                if (lane == 0) sm[SFAC + wid] = sq / (1.f + sq) / (sqrtf(sq) + 1e-8f);
            }
            __syncthreads();
            sm[SV + tid] *= sm[SFAC + (tid >> 7)];
            __syncthreads();
            {
                int d = tid & 31, b = (tid >> 5) & 7, q = tid >> 8;
                float part = 0.f;
#pragma unroll
                for (int j = 0; j < 32; j++) {
                    int e = q * 32 + j;
                    part += sm[d * 129 + e] * sm[SV + b * NE + e];
                }
                sm[SPART + (q * 8 + b) * 32 + d] = part;
            }
            __syncthreads();
            if (tid < 256) {
                int dd = tid & 31, b2 = tid >> 5;
                float wv = sm[SPART + b2 * 32 + dd] + sm[SPART + (8 + b2) * 32 + dd]
                         + sm[SPART + (16 + b2) * 32 + dd] + sm[SPART + (24 + b2) * 32 + dd];
                g_Wv[((size_t)b2 * NO + o) * ND + dc + dd] = wv;
            }
            __syncthreads();
        }
        gsync();

        // ===== apu phase: logits+softmax then pu accumulation; zero g_S
        for (int i = blk * NTHR + tid; i < NB*NO*NE; i += STRIDE) g_S[i] = 0.f;
        for (int t = blk; t < 256; t += GRID) {
            int b = t >> 5, kc = (t & 31) * 32;
            for (int i = tid; i < NO * ND; i += NTHR)
                sm[i] = g_Wv[(size_t)b * NO * ND + i];
            __syncthreads();
            int w = tid >> 5, lane = tid & 31;
            {
                int k = kc + w;
                const float* urow = u + ((size_t)b * NK + k) * ND;
                float a0 = 0, a1 = 0, a2 = 0, a3 = 0, a4 = 0, a5 = 0;
#pragma unroll 4
                for (int j = 0; j < 32; j++) {
                    int d = lane + 32 * j;
                    float uv = urow[d];
                    a0 += uv * sm[d];
                    a1 += uv * sm[ND + d];
                    a2 += uv * sm[2 * ND + d];
                    a3 += uv * sm[3 * ND + d];
                    a4 += uv * sm[4 * ND + d];
                    a5 += uv * sm[5 * ND + d];
                }
#pragma unroll
                for (int off = 16; off; off >>= 1) {
                    a0 += __shfl_xor_sync(0xffffffffu, a0, off);
                    a1 += __shfl_xor_sync(0xffffffffu, a1, off);
                    a2 += __shfl_xor_sync(0xffffffffu, a2, off);
                    a3 += __shfl_xor_sync(0xffffffffu, a3, off);
                    a4 += __shfl_xor_sync(0xffffffffu, a4, off);
                    a5 += __shfl_xor_sync(0xffffffffu, a5, off);
                }
                if (lane == 0) {
                    float av[NO] = {a0, a1, a2, a3, a4, a5};
                    size_t base = ((size_t)b * NK + k) * NO;
                    if (it == 1) {
#pragma unroll
                        for (int o = 0; o < NO; o++) av[o] += g_a[base + o];
                    }
#pragma unroll
                    for (int o = 0; o < NO; o++) g_a[base + o] = av[o];
                    float pr[NO];
                    if (mask_at(mraw, (size_t)b * NK + k)) {
#pragma unroll
                        for (int o = 0; o < NO; o++) pr[o] = 1.f / 6.f;
                    } else {
                        float m = av[0];
#pragma unroll
                        for (int o = 1; o < NO; o++) m = fmaxf(m, av[o]);
                        float ssum = 0.f;
#pragma unroll
                        for (int o = 0; o < NO; o++) { pr[o] = expf(av[o] - m); ssum += pr[o]; }
                        float inv = 1.f / ssum;
#pragma unroll
                        for (int o = 0; o < NO; o++) pr[o] *= inv;
                    }
#pragma unroll
                    for (int o = 0; o < NO; o++) {
                        g_p[base + o] = pr[o];
                        sm[SP + w * NO + o] = pr[o];
                    }
                }
            }
            __syncthreads();
            {   // phase 2: pu += p^T u over this tile's 32 k rows (u rows hot)
                const float* ucol = u + ((size_t)b * NK + kc) * ND + tid;
                float acc[NO];
#pragma unroll
                for (int o = 0; o < NO; o++) acc[o] = 0.f;
#pragma unroll 4
                for (int kk = 0; kk < 32; kk++) {
                    float uv = ucol[(size_t)kk * ND];
#pragma unroll
                    for (int o = 0; o < NO; o++) acc[o] += sm[SP + kk * NO + o] * uv;
                }
#pragma unroll
                for (int o = 0; o < NO; o++)
                    atomicAdd(&g_pu[((size_t)b * NO + o) * ND + tid], acc[o]);
            }
            __syncthreads();
        }
        gsync();
    }

    // ===== OUT: squash(S2) + broadcast outputs over L =====
    for (int i = tid; i < NB * NO * NE; i += NTHR) sm[i] = g_S[i];
    __syncthreads();
    {
        int wid = tid >> 5, lane = tid & 31;
        for (int bo = wid; bo < NB * NO; bo += 32) {
            float sq = 0.f;
#pragma unroll
            for (int j = 0; j < 4; j++) {
                float x = sm[bo * NE + lane + 32 * j];
                sq += x * x;
            }
#pragma unroll
            for (int off = 16; off; off >>= 1) sq += __shfl_xor_sync(0xffffffffu, sq, off);
            if (lane == 0) sm[SF + bo] = sq / (1.f + sq) / (sqrtf(sq) + 1e-8f);
        }
    }
    __syncthreads();
    for (int i = tid; i < NB * NO * NE; i += NTHR) sm[i] *= sm[SF + (i >> 7)];
    __syncthreads();

    // out_v: [B,L,O,E] flat float4 broadcast (192 f4 per (b,l))
    {
        const float4* sq4 = (const float4*)sm;
        for (int i = blk * NTHR + tid; i < NB * NL * 192; i += STRIDE) {
            int b = i / (NL * 192);
            int c = i % 192;
            outv[i] = sq4[b * 192 + c];
        }
    }
    __syncthreads();

    // out_p: tiles (b, 16 l): stage p[b] (24KB) then broadcast
    for (int t = blk; t < 512; t += GRID) {
        int b = t >> 6, l0 = (t & 63) * 16;
        for (int i = tid; i < NO * NK; i += NTHR)
            sm[i] = g_p[(size_t)b * NO * NK + i];
        __syncthreads();
        const float4* sp4 = (const float4*)sm;
        for (int l = 0; l < 16; l++) {
            float4* dst = outp + ((size_t)b * NL + l0 + l) * 1536;
            for (int i = tid; i < 1536; i += NTHR) dst[i] = sp4[i];
        }
        __syncthreads();
    }
}

// ---------------------------------------------------------------------------
extern "C" void kernel_launch(void* const* d_in, const int* in_sizes, int n_in,
                              void* d_out, int out_size) {
    const float*         u    = (const float*)d_in[0];
    // d_in[1] = context_sequence: unused (result is independent of L content)
    const float*         W    = (const float*)d_in[2];
    const unsigned char* mask = (const unsigned char*)d_in[3];

    float* out   = (float*)d_out;
    float4* outv = (float4*)out;                               // [B,L,O,E]
    float4* outp = (float4*)(out + (size_t)NB * NL * NO * NE); // [B,L,K,O]

    k_all<<<GRID, NTHR>>>(u, W, mask, outv, outp);

    (void)in_sizes; (void)n_in; (void)out_size;
}

// round 10
// speedup vs baseline: 1.1518x; 1.1518x over previous
#include <cuda_runtime.h>
#include <math.h>

// Problem constants
#define NB 8
#define NK 1024
#define NL 1024
#define ND 1024
#define NO 6
#define NE 128

// Scratch (tiny): everything l-independent
__device__ __align__(16) float g_S [NB*NO*NE];   // raw vote sum   [b,o,e]
__device__ __align__(16) float g_Wv[NB*NO*ND];   // W @ v          [b,o,d]
__device__ __align__(16) float g_a [NB*NK*NO];   // logits         [b,k,o]
__device__ __align__(16) float g_p [NB*NK*NO];   // probs          [b,k,o]
__device__ __align__(16) float g_pu[NB*NO*ND];   // p^T @ u        [b,o,d]
__device__ int g_mask_is_u8;                     // mask dtype flag

// ---------------------------------------------------------------------------
// Prolog: zero g_pu & g_S, detect mask dtype.
__global__ void k_prolog(const unsigned char* __restrict__ mraw) {
    int i = blockIdx.x * 256 + threadIdx.x;
    if (i < NB*NO*ND) g_pu[i] = 0.f;
    if (i < NB*NO*NE) g_S[i]  = 0.f;
    if (blockIdx.x == 0 && threadIdx.x == 0) {
        int u8 = 0;
        for (int j = 0; j < 256; j++)
            if ((j & 3) != 0 && mraw[j] != 0) u8 = 1;
        g_mask_is_u8 = u8;
    }
}

__device__ __forceinline__ int mask_at(const unsigned char* mraw, size_t idx) {
    if (g_mask_is_u8) return mraw[idx] != 0;
    return ((const int*)mraw)[idx] != 0;
}

// ---------------------------------------------------------------------------
// Iteration-0 shortcut: p0 = 1/6 uniformly, so pu0[b,o,d] = (1/6)*sum_k u —
// o-independent. Compute colsum into g_pu[b][o=0][:].
// grid (NB, ND/256, 16), block 256
__global__ void k_colsum(const float* __restrict__ u) {
    int b  = blockIdx.x;
    int d  = blockIdx.y * 256 + threadIdx.x;
    int kb = blockIdx.z * 64;
    const float* up = u + ((size_t)b * NK + kb) * ND + d;
    float acc = 0.f;
#pragma unroll 8
    for (int kk = 0; kk < 64; kk++) acc += up[(size_t)kk * ND];
    atomicAdd(&g_pu[(size_t)b * NO * ND + d], acc);
}

// ---------------------------------------------------------------------------
// S[b,o,e] += sum_{d in 16-chunk} pu[b,o,d] * W[o,d,e] for all 8 b at once.
// FIRST: read o-independent colsum (o=0 row) scaled by 1/6.
// grid (NO, ND/16), block 128.
template <int FIRST>
__global__ void k_S(const float* __restrict__ W) {
    __shared__ float spu[NB][16];
    int o  = blockIdx.x;
    int dc = blockIdx.y * 16;
    int e  = threadIdx.x;

    {   // 128 threads load exactly 128 entries
        int b = threadIdx.x >> 4, dd = threadIdx.x & 15;
        float v = FIRST ? g_pu[(size_t)b * NO * ND + dc + dd] * (1.f / 6.f)
                        : g_pu[((size_t)b * NO + o) * ND + dc + dd];
        spu[b][dd] = v;
    }
    __syncthreads();

    float acc[NB];
#pragma unroll
    for (int b = 0; b < NB; b++) acc[b] = 0.f;

    const float* Wo = W + ((size_t)o * ND + dc) * NE + e;
#pragma unroll
    for (int dd = 0; dd < 16; dd++) {
        float w = Wo[(size_t)dd * NE];
#pragma unroll
        for (int b = 0; b < NB; b++) acc[b] += spu[b][dd] * w;
    }
#pragma unroll
    for (int b = 0; b < NB; b++)
        atomicAdd(&g_S[((size_t)b * NO + o) * NE + e], acc[b]);
}

// ---------------------------------------------------------------------------
// Fused squash + Wv (R6-proven shape): v = squash(S) per-block, then
// Wv[b,o,d] = sum_e W[o,d,e]*v[b,o,e] for all 8 b (W row read once).
// Also zeroes g_pu for the next k_apu (768 blocks x 64 floats).
// grid (NO, ND/8), block 256 = 8 warps (warp = one d)
__global__ void k_WvSq(const float* __restrict__ W) {
    __shared__ float sv[NB][NE];   // 4 KB
    __shared__ float sfac[NB];
    int o = blockIdx.x;
    int wid = threadIdx.x >> 5, lane = threadIdx.x & 31;

    // zero g_pu slice: 49152 / 768 blocks = 64 floats per block
    {
        int slice = blockIdx.x * (ND / 8) + blockIdx.y;   // 0..767
        if (threadIdx.x < 64) g_pu[(size_t)slice * 64 + threadIdx.x] = 0.f;
    }

    for (int i = threadIdx.x; i < NB * NE; i += 256)
        sv[i >> 7][i & 127] = g_S[((size_t)(i >> 7) * NO + o) * NE + (i & 127)];
    __syncthreads();

    // warp w computes squash factor for b=w
    {
        float sq = 0.f;
#pragma unroll
        for (int j = 0; j < 4; j++) {
            float x = sv[wid][lane + 32 * j];
            sq += x * x;
        }
#pragma unroll
        for (int off = 16; off; off >>= 1) sq += __shfl_xor_sync(0xffffffffu, sq, off);
        if (lane == 0) sfac[wid] = sq / (1.f + sq) / (sqrtf(sq) + 1e-8f);
    }
    __syncthreads();
    for (int i = threadIdx.x; i < NB * NE; i += 256)
        sv[i >> 7][i & 127] *= sfac[i >> 7];
    __syncthreads();

    int d = blockIdx.y * 8 + wid;
    const float* Wrow = W + ((size_t)o * ND + d) * NE;
    float wv[4];
#pragma unroll
    for (int j = 0; j < 4; j++) wv[j] = Wrow[lane + 32 * j];

#pragma unroll
    for (int b = 0; b < NB; b++) {
        float s = 0.f;
#pragma unroll
        for (int j = 0; j < 4; j++) s += wv[j] * sv[b][lane + 32 * j];
#pragma unroll
        for (int off = 16; off; off >>= 1) s += __shfl_xor_sync(0xffffffffu, s, off);
        if (lane == 0) g_Wv[((size_t)b * NO + o) * ND + d] = s;
    }
}

// ---------------------------------------------------------------------------
// Fused agreement + softmax + pu-accumulation:
//  phase 1: a[b,k,o] (+)= sum_d u[b,k,d]*Wv[b,o,d]; p = masked softmax (->smem+g_p)
//  phase 2: pu[b,o,d] += sum_{k in block} p[k,o]*u[b,k,d]  (u rows hot in L1/L2)
// Also zeroes g_S slices for the next k_S.
// grid (NB, NK/16) = 512 blocks, block 256 = 8 warps, each warp does 2 k's.
template <int ACCUM>
__global__ void k_apu(const float* __restrict__ u,
                      const unsigned char* __restrict__ mraw) {
    __shared__ float sWv[NO * ND];  // 24 KB
    __shared__ float sp[16][NO];
    int b  = blockIdx.x;
    int kb = blockIdx.y * 16;

    // zero g_S slice: 6144 / 512 blocks = 12 floats each
    {
        int slice = blockIdx.x * 64 + blockIdx.y;   // 0..511
        if (threadIdx.x < 12) g_S[(size_t)slice * 12 + threadIdx.x] = 0.f;
    }

    for (int i = threadIdx.x; i < NO * ND; i += 256)
        sWv[i] = g_Wv[(size_t)b * NO * ND + i];
    __syncthreads();

    int warp = threadIdx.x >> 5, lane = threadIdx.x & 31;

    for (int ki = 0; ki < 2; ki++) {
        int k = kb + warp * 2 + ki;
        const float* urow = u + ((size_t)b * NK + k) * ND;
        float a0 = 0, a1 = 0, a2 = 0, a3 = 0, a4 = 0, a5 = 0;
#pragma unroll 4
        for (int j = 0; j < 32; j++) {
            int d = lane + 32 * j;
            float uv = urow[d];
            a0 += uv * sWv[d];
            a1 += uv * sWv[ND + d];
            a2 += uv * sWv[2 * ND + d];
            a3 += uv * sWv[3 * ND + d];
            a4 += uv * sWv[4 * ND + d];
            a5 += uv * sWv[5 * ND + d];
        }
#pragma unroll
        for (int off = 16; off; off >>= 1) {
            a0 += __shfl_xor_sync(0xffffffffu, a0, off);
            a1 += __shfl_xor_sync(0xffffffffu, a1, off);
            a2 += __shfl_xor_sync(0xffffffffu, a2, off);
            a3 += __shfl_xor_sync(0xffffffffu, a3, off);
            a4 += __shfl_xor_sync(0xffffffffu, a4, off);
            a5 += __shfl_xor_sync(0xffffffffu, a5, off);
        }
        if (lane == 0) {
            float av[NO] = {a0, a1, a2, a3, a4, a5};
            size_t base = ((size_t)b * NK + k) * NO;
            if (ACCUM) {
#pragma unroll
                for (int o = 0; o < NO; o++) av[o] += g_a[base + o];
            }
#pragma unroll
            for (int o = 0; o < NO; o++) g_a[base + o] = av[o];

            float pr[NO];
            if (mask_at(mraw, (size_t)b * NK + k)) {
#pragma unroll
                for (int o = 0; o < NO; o++) pr[o] = 1.f / 6.f;
            } else {
                float m = av[0];
#pragma unroll
                for (int o = 1; o < NO; o++) m = fmaxf(m, av[o]);
                float ssum = 0.f;
#pragma unroll
                for (int o = 0; o < NO; o++) { pr[o] = expf(av[o] - m); ssum += pr[o]; }
                float inv = 1.f / ssum;
#pragma unroll
                for (int o = 0; o < NO; o++) pr[o] *= inv;
            }
#pragma unroll
            for (int o = 0; o < NO; o++) {
                g_p[base + o] = pr[o];
                sp[warp * 2 + ki][o] = pr[o];
            }
        }
    }
    __syncthreads();

    // phase 2: pu accumulation over this block's 16 k rows (hot in L1/L2)
#pragma unroll
    for (int dj = 0; dj < 4; dj++) {
        int d = dj * 256 + threadIdx.x;
        const float* ucol = u + ((size_t)b * NK + kb) * ND + d;
        float acc[NO];
#pragma unroll
        for (int o = 0; o < NO; o++) acc[o] = 0.f;
#pragma unroll 4
        for (int kk = 0; kk < 16; kk++) {
            float uv = ucol[(size_t)kk * ND];
#pragma unroll
            for (int o = 0; o < NO; o++) acc[o] += sp[kk][o] * uv;
        }
#pragma unroll
        for (int o = 0; o < NO; o++)
            atomicAdd(&g_pu[((size_t)b * NO + o) * ND + d], acc[o]);
    }
}

// ---------------------------------------------------------------------------
// Fused final output: squash(S) + broadcast BOTH outputs over L.
// outputs_v[b,l,o,e] = squash(S)[b,o,e]; probs[b,l,k,o] = p[b,k,o].
// grid (NB, NL/16), block 256
__global__ void k_out(float4* __restrict__ outv, float4* __restrict__ outp) {
    __shared__ float4 spp[NK * NO / 4];          // 1536 float4 = 24 KB
    __shared__ __align__(16) float sv[NO * NE];  // 768 floats
    __shared__ float sfac[NO];
    int b  = blockIdx.x;
    int lb = blockIdx.y * 16;
    int wid = threadIdx.x >> 5, lane = threadIdx.x & 31;

    // stage p[b]
    const float4* psrc = (const float4*)(g_p + (size_t)b * NK * NO);
    for (int i = threadIdx.x; i < 1536; i += 256) spp[i] = psrc[i];

    // stage S[b] and squash
    for (int i = threadIdx.x; i < NO * NE; i += 256)
        sv[i] = g_S[(size_t)b * NO * NE + i];
    __syncthreads();

    if (wid < NO) {
        float sq = 0.f;
#pragma unroll
        for (int j = 0; j < 4; j++) {
            float x = sv[wid * NE + lane + 32 * j];
            sq += x * x;
        }
#pragma unroll
        for (int off = 16; off; off >>= 1) sq += __shfl_xor_sync(0xffffffffu, sq, off);
        if (lane == 0) sfac[wid] = sq / (1.f + sq) / (sqrtf(sq) + 1e-8f);
    }
    __syncthreads();
    for (int i = threadIdx.x; i < NO * NE; i += 256)
        sv[i] *= sfac[i >> 7];
    __syncthreads();

    // write outputs_v: 16 l x 192 float4
    const float4* sv4 = (const float4*)sv;
    for (int idx = threadIdx.x; idx < 16 * 192; idx += 256) {
        int l = idx / 192, c = idx % 192;
        outv[((size_t)b * NL + lb + l) * 192 + c] = sv4[c];
    }

    // write probs: 16 l x 1536 float4
    for (int l = 0; l < 16; l++) {
        float4* dst = outp + ((size_t)b * NL + lb + l) * 1536;
#pragma unroll 2
        for (int i = threadIdx.x; i < 1536; i += 256) dst[i] = spp[i];
    }
}

// ---------------------------------------------------------------------------
extern "C" void kernel_launch(void* const* d_in, const int* in_sizes, int n_in,
                              void* d_out, int out_size) {
    const float*         u    = (const float*)d_in[0];
    // d_in[1] = context_sequence: unused (result is independent of L content)
    const float*         W    = (const float*)d_in[2];
    const unsigned char* mask = (const unsigned char*)d_in[3];

    float* out   = (float*)d_out;
    float4* outv = (float4*)out;                               // [B,L,O,E]
    float4* outp = (float4*)(out + (size_t)NB * NL * NO * NE); // [B,L,K,O]

    dim3 b256(256);
    dim3 gCS(NB, ND / 256, 16);
    dim3 gS(NO, ND / 16);
    dim3 gWv(NO, ND / 8);
    dim3 gAP(NB, NK / 16);

    // iteration 0: uniform p -> colsum shortcut
    k_prolog<<<192, b256>>>(mask);
    k_colsum<<<gCS, b256>>>(u);
    k_S<1><<<gS, 128>>>(W);
    k_WvSq<<<gWv, b256>>>(W);                   // v0 -> Wv0; zero pu
    k_apu<0><<<gAP, b256>>>(u, mask);           // a=u.Wv0, p1, pu1; zero S

    // iteration 1
    k_S<0><<<gS, 128>>>(W);
    k_WvSq<<<gWv, b256>>>(W);                   // v1 -> Wv1; zero pu
    k_apu<1><<<gAP, b256>>>(u, mask);           // a+=u.Wv1, p2, pu2; zero S

    // iteration 2 (final): v2 from p2
    k_S<0><<<gS, 128>>>(W);

    // fused outputs: squash + both broadcasts
    k_out<<<dim3(NB, NL / 16), b256>>>(outv, outp);

    (void)in_sizes; (void)n_in; (void)out_size;
}